// round 4
// baseline (speedup 1.0000x reference)
#include <cuda_runtime.h>
#include <cstdint>
#include <cstddef>

// VQ: encodings (16,32,32,64) f32 -> N=16384 pts, D=64; codebook (8192,64) f32.
// dist_j = ||c_j||^2 - 2 x.c_j  (x^2 term is argmin-invariant). Output = codebook[argmin].

#define N_PTS   16384
#define DIMS    64
#define K_CODES 8192
#define TM      128           // points per block
#define TK      128           // codes per tile
#define NTILES  (K_CODES / TK)
#define NTHREADS 256
#define ROWSTRIDE 132         // padded smem row stride (floats)
#define SMEM_BYTES (2 * DIMS * ROWSTRIDE * sizeof(float))   // 67584 B

__device__ float g_csq[K_CODES];

// ---- c_sq precompute -------------------------------------------------------
__global__ void __launch_bounds__(256) csq_kernel(const float* __restrict__ cb) {
    int i = blockIdx.x * blockDim.x + threadIdx.x;
    if (i >= K_CODES) return;
    const float4* row = reinterpret_cast<const float4*>(cb + (size_t)i * DIMS);
    float s = 0.f;
#pragma unroll
    for (int q = 0; q < DIMS / 4; q++) {
        float4 v = row[q];
        s += v.x * v.x + v.y * v.y + v.z * v.z + v.w * v.w;
    }
    g_csq[i] = s;
}

// ---- packed f32x2 helpers ---------------------------------------------------
#define FMA2(a, b, c) asm("fma.rn.f32x2 %0, %1, %2, %0;" : "+l"(a) : "l"(b), "l"(c))

__device__ __forceinline__ unsigned long long dup_f32(float c) {
    unsigned long long r;
    asm("mov.b64 %0, {%1, %1};" : "=l"(r) : "f"(c));
    return r;
}

// ---- main kernel ------------------------------------------------------------
__global__ void __launch_bounds__(NTHREADS, 1) vq_kernel(
    const float* __restrict__ enc,
    const float* __restrict__ cb,
    float* __restrict__ out)
{
    extern __shared__ float smem[];
    float* sp = smem;                     // points, transposed [64][132]
    float* sc = smem + DIMS * ROWSTRIDE;  // codes,  transposed [64][132]

    const int tid = threadIdx.x;
    const int tx  = tid & 15;   // code-group (8 codes)
    const int ty  = tid >> 4;   // point-group (8 points)
    const int pbase = blockIdx.x * TM;

    // load-phase mapping: lane-contiguous rows -> conflict-free transposed stores
    const int lp = tid & 127;   // point / code row
    const int lh = tid >> 7;    // half of the 64 dims

    // --- load point tile (transposed into sp) ---
    {
        const float4* src = reinterpret_cast<const float4*>(
            enc + (size_t)(pbase + lp) * DIMS + lh * 32);
#pragma unroll
        for (int q = 0; q < 8; q++) {
            float4 v = src[q];
            int d0 = lh * 32 + q * 4;
            sp[(d0 + 0) * ROWSTRIDE + lp] = v.x;
            sp[(d0 + 1) * ROWSTRIDE + lp] = v.y;
            sp[(d0 + 2) * ROWSTRIDE + lp] = v.z;
            sp[(d0 + 3) * ROWSTRIDE + lp] = v.w;
        }
    }

    // --- load code tile 0 (transposed into sc) ---
    float4 pre[8];
    {
        const float4* src = reinterpret_cast<const float4*>(
            cb + (size_t)lp * DIMS + lh * 32);
#pragma unroll
        for (int q = 0; q < 8; q++) pre[q] = src[q];
#pragma unroll
        for (int q = 0; q < 8; q++) {
            int d0 = lh * 32 + q * 4;
            sc[(d0 + 0) * ROWSTRIDE + lp] = pre[q].x;
            sc[(d0 + 1) * ROWSTRIDE + lp] = pre[q].y;
            sc[(d0 + 2) * ROWSTRIDE + lp] = pre[q].z;
            sc[(d0 + 3) * ROWSTRIDE + lp] = pre[q].w;
        }
    }

    float bmin[8];
    int   bidx[8];
#pragma unroll
    for (int i = 0; i < 8; i++) { bmin[i] = 3.402823466e38f; bidx[i] = 0; }

#pragma unroll 1
    for (int t = 0; t < NTILES; t++) {
        __syncthreads();   // sc now holds tile t (and sp on t==0)

        // prefetch c_sq for this tile's 8 codes (L2, ready by epilogue)
        float4 cs0 = *reinterpret_cast<const float4*>(g_csq + t * TK + tx * 8);
        float4 cs1 = *reinterpret_cast<const float4*>(g_csq + t * TK + tx * 8 + 4);

        // prefetch next code tile into registers (latency hidden by compute)
        if (t + 1 < NTILES) {
            const float4* src = reinterpret_cast<const float4*>(
                cb + ((size_t)(t + 1) * TK + lp) * DIMS + lh * 32);
#pragma unroll
            for (int q = 0; q < 8; q++) pre[q] = src[q];
        }

        // --- 8 pts x 8 codes micro-tile, f32x2 packed over the point pairs ---
        unsigned long long acc[4][8];
#pragma unroll
        for (int pp = 0; pp < 4; pp++)
#pragma unroll
            for (int j = 0; j < 8; j++) acc[pp][j] = 0ull;

#pragma unroll 4
        for (int d = 0; d < DIMS; d++) {
            const unsigned long long* pr = reinterpret_cast<const unsigned long long*>(
                sp + d * ROWSTRIDE + ty * 8);
            unsigned long long p0 = pr[0], p1 = pr[1], p2 = pr[2], p3 = pr[3];
            const float* cr = sc + d * ROWSTRIDE + tx * 8;
            float4 c0 = *reinterpret_cast<const float4*>(cr);
            float4 c1 = *reinterpret_cast<const float4*>(cr + 4);
            float cf[8] = {c0.x, c0.y, c0.z, c0.w, c1.x, c1.y, c1.z, c1.w};
#pragma unroll
            for (int j = 0; j < 8; j++) {
                unsigned long long cd = dup_f32(cf[j]);
                FMA2(acc[0][j], p0, cd);
                FMA2(acc[1][j], p1, cd);
                FMA2(acc[2][j], p2, cd);
                FMA2(acc[3][j], p3, cd);
            }
        }

        // --- epilogue: dist = c_sq - 2*dot; strict < keeps earliest index ---
        float cs[8] = {cs0.x, cs0.y, cs0.z, cs0.w, cs1.x, cs1.y, cs1.z, cs1.w};
#pragma unroll
        for (int j = 0; j < 8; j++) {
            int gidx = t * TK + tx * 8 + j;
#pragma unroll
            for (int pp = 0; pp < 4; pp++) {
                float lo, hi;
                asm("mov.b64 {%0, %1}, %2;" : "=f"(lo), "=f"(hi) : "l"(acc[pp][j]));
                float dl = fmaf(-2.f, lo, cs[j]);
                float dh = fmaf(-2.f, hi, cs[j]);
                int i0 = pp * 2, i1 = pp * 2 + 1;
                if (dl < bmin[i0]) { bmin[i0] = dl; bidx[i0] = gidx; }
                if (dh < bmin[i1]) { bmin[i1] = dh; bidx[i1] = gidx; }
            }
        }

        __syncthreads();   // everyone done reading sc tile t
        if (t + 1 < NTILES) {
#pragma unroll
            for (int q = 0; q < 8; q++) {
                int d0 = lh * 32 + q * 4;
                sc[(d0 + 0) * ROWSTRIDE + lp] = pre[q].x;
                sc[(d0 + 1) * ROWSTRIDE + lp] = pre[q].y;
                sc[(d0 + 2) * ROWSTRIDE + lp] = pre[q].z;
                sc[(d0 + 3) * ROWSTRIDE + lp] = pre[q].w;
            }
        }
    }

    // --- cross-thread (tx) argmin reduce; reuse sp region (all reads done) ---
    float* rmin = sp;                                 // [128][16] floats
    int*   ridx = reinterpret_cast<int*>(sp + TM * 16); // [128][16] ints
#pragma unroll
    for (int i = 0; i < 8; i++) {
        rmin[(ty * 8 + i) * 16 + tx] = bmin[i];
        ridx[(ty * 8 + i) * 16 + tx] = bidx[i];
    }
    __syncthreads();
    if (tid < TM) {
        float m  = rmin[tid * 16];
        int   mi = ridx[tid * 16];
#pragma unroll
        for (int x = 1; x < 16; x++) {
            float v  = rmin[tid * 16 + x];
            int   vi = ridx[tid * 16 + x];
            if (v < m || (v == m && vi < mi)) { m = v; mi = vi; }
        }
        ridx[tid * 16] = mi;   // publish winning index
    }
    __syncthreads();

    // --- gather: out[p] = codebook[idx[p]] (exact row copy) ---
    {
        int ci = ridx[lp * 16];
        const float4* src = reinterpret_cast<const float4*>(
            cb + (size_t)ci * DIMS + lh * 32);
        float4* dst = reinterpret_cast<float4*>(
            out + (size_t)(pbase + lp) * DIMS + lh * 32);
#pragma unroll
        for (int q = 0; q < 8; q++) dst[q] = src[q];
    }
}

// ---- launcher ---------------------------------------------------------------
extern "C" void kernel_launch(void* const* d_in, const int* in_sizes, int n_in,
                              void* d_out, int out_size) {
    const float* enc = (const float*)d_in[0];   // 16*32*32*64 = 1048576
    const float* cb  = (const float*)d_in[1];   // 8192*64     = 524288
    float* out = (float*)d_out;

    static bool attr_set = false;
    if (!attr_set) {
        cudaFuncSetAttribute(vq_kernel, cudaFuncAttributeMaxDynamicSharedMemorySize,
                             (int)SMEM_BYTES);
        attr_set = true;
    }

    csq_kernel<<<K_CODES / 256, 256>>>(cb);
    vq_kernel<<<N_PTS / TM, NTHREADS, SMEM_BYTES>>>(enc, cb, out);
}

// round 6
// speedup vs baseline: 1.1180x; 1.1180x over previous
#include <cuda_runtime.h>
#include <cstdint>
#include <cstddef>

// VQ: encodings (16,32,32,64) f32 -> N=16384 pts, D=64; codebook (8192,64) f32.
// dist_j = ||c_j||^2 - 2 x.c_j (x^2 is argmin-invariant). Output = codebook[argmin].

#define N_PTS    16384
#define DIMS     64
#define K_CODES  8192
#define TM       128            // points per block
#define TK       256            // codes per tile
#define NTILES   (K_CODES / TK) // 32
#define NTHREADS 256
#define SP_STRIDE 132                       // padded point-row stride (floats)
#define SP_BYTES  (DIMS * SP_STRIDE * 4)    // 33792
#define SC_BYTES  (DIMS * TK * 4)           // 65536 per buffer (row = 1024 B, swizzled)
#define SMEM_BYTES (SP_BYTES + 2 * SC_BYTES) // 164864

__device__ __align__(16) float g_csq[K_CODES];

// ---- c_sq precompute --------------------------------------------------------
__global__ void __launch_bounds__(256) csq_kernel(const float* __restrict__ cb) {
    int i = blockIdx.x * blockDim.x + threadIdx.x;
    if (i >= K_CODES) return;
    const float4* row = reinterpret_cast<const float4*>(cb + (size_t)i * DIMS);
    float s = 0.f;
#pragma unroll
    for (int q = 0; q < DIMS / 4; q++) {
        float4 v = row[q];
        s += v.x * v.x + v.y * v.y + v.z * v.z + v.w * v.w;
    }
    g_csq[i] = s;
}

// ---- packed f32x2 helpers ----------------------------------------------------
#define FMA2(a, b, c) asm("fma.rn.f32x2 %0, %1, %2, %0;" : "+l"(a) : "l"(b), "l"(c))

__device__ __forceinline__ unsigned long long dup_f32(float c) {
    unsigned long long r;
    asm("mov.b64 %0, {%1, %1};" : "=l"(r) : "f"(c));
    return r;
}
__device__ __forceinline__ float2 u2f2(unsigned long long u) {
    float2 f;
    asm("mov.b64 {%0, %1}, %2;" : "=f"(f.x), "=f"(f.y) : "l"(u));
    return f;
}
// conflict-free swizzle within a 1024-B smem row (XOR 16B-chunk by 128B-row bits)
__device__ __forceinline__ int swz(int b) { return b ^ ((b >> 3) & 0x70); }

// ---- main kernel --------------------------------------------------------------
__global__ void __launch_bounds__(NTHREADS, 1) vq_kernel(
    const float* __restrict__ enc,
    const float* __restrict__ cb,
    float* __restrict__ out)
{
    extern __shared__ char smem[];
    float* sp  = reinterpret_cast<float*>(smem);      // points, transposed [64][132]
    char*  scb = smem + SP_BYTES;                     // 2 code buffers [64][1024B], swizzled

    const int tid = threadIdx.x;
    const int tx  = tid & 15;    // code-group: 16 codes
    const int ty  = tid >> 4;    // point-group: 8 points
    const int pbase = blockIdx.x * TM;

    const int lp = tid & 127;    // point row for load/gather phases
    const int lh = tid >> 7;     // dim half

    // --- load point tile (transposed into sp) ---
    {
        const float4* src = reinterpret_cast<const float4*>(
            enc + (size_t)(pbase + lp) * DIMS + lh * 32);
#pragma unroll
        for (int q = 0; q < 8; q++) {
            float4 v = src[q];
            int d0 = lh * 32 + q * 4;
            sp[(d0 + 0) * SP_STRIDE + lp] = v.x;
            sp[(d0 + 1) * SP_STRIDE + lp] = v.y;
            sp[(d0 + 2) * SP_STRIDE + lp] = v.z;
            sp[(d0 + 3) * SP_STRIDE + lp] = v.w;
        }
    }

    // per-thread constant smem offsets (swizzle applied once)
    const int so = swz(4 * tid);              // store offset: code column `tid`
    const int r0 = swz(64 * tx + 0);          // read offsets: 4x 16B chunks
    const int r1 = swz(64 * tx + 16);
    const int r2 = swz(64 * tx + 32);
    const int r3 = swz(64 * tx + 48);

    // --- load code tile 0 into buffer 0 (thread -> code row `tid`) ---
    {
        const float4* src = reinterpret_cast<const float4*>(cb + (size_t)tid * DIMS);
        char* dst = scb + so;
#pragma unroll
        for (int q = 0; q < 16; q++) {
            float4 v = src[q];
            int d0 = q * 4;
            *reinterpret_cast<float*>(dst + (d0 + 0) * 1024) = v.x;
            *reinterpret_cast<float*>(dst + (d0 + 1) * 1024) = v.y;
            *reinterpret_cast<float*>(dst + (d0 + 2) * 1024) = v.z;
            *reinterpret_cast<float*>(dst + (d0 + 3) * 1024) = v.w;
        }
    }

    float bmin[8];
    int   bidx[8];
#pragma unroll
    for (int i = 0; i < 8; i++) { bmin[i] = 3.402823466e38f; bidx[i] = 0; }

#pragma unroll 1
    for (int t = 0; t < NTILES; t++) {
        __syncthreads();   // cur buffer ready; prior reads of nxt buffer done
        char* cur = scb + (size_t)(t & 1) * SC_BYTES;
        char* nxt = scb + (size_t)((t + 1) & 1) * SC_BYTES;
        const bool pf = (t + 1 < NTILES);
        const float4* nsrc = reinterpret_cast<const float4*>(
            cb + ((size_t)(t + 1) * TK + tid) * DIMS);

        // c_sq for this tile's 16 codes
        float4 cs[4];
#pragma unroll
        for (int q = 0; q < 4; q++)
            cs[q] = *reinterpret_cast<const float4*>(g_csq + t * TK + tx * 16 + q * 4);

        unsigned long long acc[4][16];
#pragma unroll
        for (int pp = 0; pp < 4; pp++)
#pragma unroll
            for (int j = 0; j < 16; j++) acc[pp][j] = 0ull;

        // 4 segments of 16 dims; each segment prefetches a quarter of tile t+1
#pragma unroll 1
        for (int seg = 0; seg < 4; seg++) {
            const int dbase = seg * 16;
            float4 pfv[4];
            if (pf) {
#pragma unroll
                for (int q = 0; q < 4; q++) pfv[q] = nsrc[seg * 4 + q];
            }

#pragma unroll 4
            for (int dd = 0; dd < 16; dd++) {
                const int d = dbase + dd;
                const ulonglong2* pr = reinterpret_cast<const ulonglong2*>(
                    sp + d * SP_STRIDE + ty * 8);
                ulonglong2 pa = pr[0];     // point pairs 0-1, 2-3
                ulonglong2 pb = pr[1];     // point pairs 4-5, 6-7
                const char* crow = cur + d * 1024;
                float4 c0 = *reinterpret_cast<const float4*>(crow + r0);
                float4 c1 = *reinterpret_cast<const float4*>(crow + r1);
                float4 c2 = *reinterpret_cast<const float4*>(crow + r2);
                float4 c3 = *reinterpret_cast<const float4*>(crow + r3);
                float cf[16] = {c0.x, c0.y, c0.z, c0.w, c1.x, c1.y, c1.z, c1.w,
                                c2.x, c2.y, c2.z, c2.w, c3.x, c3.y, c3.z, c3.w};
#pragma unroll
                for (int j = 0; j < 16; j++) {
                    unsigned long long cd = dup_f32(cf[j]);
                    FMA2(acc[0][j], pa.x, cd);
                    FMA2(acc[1][j], pa.y, cd);
                    FMA2(acc[2][j], pb.x, cd);
                    FMA2(acc[3][j], pb.y, cd);
                }
            }

            if (pf) {  // store prefetched quarter into the other buffer (no barrier needed)
                char* dst = nxt + so;
#pragma unroll
                for (int q = 0; q < 4; q++) {
                    int d0 = dbase + q * 4;
                    *reinterpret_cast<float*>(dst + (d0 + 0) * 1024) = pfv[q].x;
                    *reinterpret_cast<float*>(dst + (d0 + 1) * 1024) = pfv[q].y;
                    *reinterpret_cast<float*>(dst + (d0 + 2) * 1024) = pfv[q].z;
                    *reinterpret_cast<float*>(dst + (d0 + 3) * 1024) = pfv[q].w;
                }
            }
        }

        // --- epilogue: dist = c_sq - 2*dot; strict < keeps earliest index ---
        const float* csf = reinterpret_cast<const float*>(cs);
#pragma unroll
        for (int j = 0; j < 16; j++) {
            int gidx = t * TK + tx * 16 + j;
            float csv = csf[j];
#pragma unroll
            for (int pp = 0; pp < 4; pp++) {
                float2 v = u2f2(acc[pp][j]);
                float dl = fmaf(-2.f, v.x, csv);
                float dh = fmaf(-2.f, v.y, csv);
                int i0 = pp * 2, i1 = pp * 2 + 1;
                if (dl < bmin[i0]) { bmin[i0] = dl; bidx[i0] = gidx; }
                if (dh < bmin[i1]) { bmin[i1] = dh; bidx[i1] = gidx; }
            }
        }
    }
    __syncthreads();   // all smem reads done; safe to reuse sp for reduction

    // --- cross-thread (tx) argmin reduce in sp region ---
    float* rmin = sp;                                   // [128][16]
    int*   ridx = reinterpret_cast<int*>(sp + TM * 16); // [128][16]
#pragma unroll
    for (int i = 0; i < 8; i++) {
        rmin[(ty * 8 + i) * 16 + tx] = bmin[i];
        ridx[(ty * 8 + i) * 16 + tx] = bidx[i];
    }
    __syncthreads();
    if (tid < TM) {
        float m  = rmin[tid * 16];
        int   mi = ridx[tid * 16];
#pragma unroll
        for (int x = 1; x < 16; x++) {
            float v  = rmin[tid * 16 + x];
            int   vi = ridx[tid * 16 + x];
            if (v < m || (v == m && vi < mi)) { m = v; mi = vi; }
        }
        ridx[tid * 16] = mi;
    }
    __syncthreads();

    // --- gather: out[p] = codebook[argmin] (exact row copy) ---
    {
        int ci = ridx[lp * 16];
        const float4* src = reinterpret_cast<const float4*>(
            cb + (size_t)ci * DIMS + lh * 32);
        float4* dst = reinterpret_cast<float4*>(
            out + (size_t)(pbase + lp) * DIMS + lh * 32);
#pragma unroll
        for (int q = 0; q < 8; q++) dst[q] = src[q];
    }
}

// ---- launcher -----------------------------------------------------------------
extern "C" void kernel_launch(void* const* d_in, const int* in_sizes, int n_in,
                              void* d_out, int out_size) {
    const float* enc = (const float*)d_in[0];   // 16*32*32*64
    const float* cb  = (const float*)d_in[1];   // 8192*64
    float* out = (float*)d_out;

    static bool attr_set = false;
    if (!attr_set) {
        cudaFuncSetAttribute(vq_kernel, cudaFuncAttributeMaxDynamicSharedMemorySize,
                             (int)SMEM_BYTES);
        attr_set = true;
    }

    csq_kernel<<<K_CODES / 256, 256>>>(cb);
    vq_kernel<<<N_PTS / TM, NTHREADS, SMEM_BYTES>>>(enc, cb, out);
}

// round 10
// speedup vs baseline: 1.2457x; 1.1142x over previous
#include <cuda_runtime.h>
#include <cstdint>
#include <cstddef>

// VQ via legacy warp-level mma.sync (tf32, 3-split) — sm_103 non-'a' target safe.
// dist_j = ||c_j||^2 - 2 x.c_j ; dot = x_hi.c_hi + x_hi.c_lo + x_lo.c_hi (tf32 mma, f32 acc).

#define N_PTS    16384
#define DIMS     64
#define K_CODES  8192
#define TM       128               // points per CTA
#define TK       128               // codes per tile
#define NTILES   (K_CODES / TK)    // 64
#define NTHREADS 256

#define SC_STRIDE 68                              // floats per code row (pad: conflict-free)
#define SC_SPLIT  (TK * SC_STRIDE * 4)            // 34816 B per split per buffer
#define SM_CSQ    0                               // 2 x 128 f32
#define SM_IDX    1024                            // 128 i32
#define SM_B      2048
#define SMEM_BYTES (SM_B + 4 * SC_SPLIT)          // 141312

__device__ __align__(16) float g_csq[K_CODES];

// ---- csq precompute (exact fp32) ----
__global__ void __launch_bounds__(256) csq_kernel(const float* __restrict__ cb) {
    int i = blockIdx.x * blockDim.x + threadIdx.x;
    if (i >= K_CODES) return;
    const float4* row = reinterpret_cast<const float4*>(cb + (size_t)i * DIMS);
    float s = 0.f;
#pragma unroll
    for (int q = 0; q < DIMS / 4; q++) {
        float4 v = row[q];
        s += v.x * v.x + v.y * v.y + v.z * v.z + v.w * v.w;
    }
    g_csq[i] = s;
}

// ---- tf32 split ----
__device__ __forceinline__ void tf32_split(float x, uint32_t& hi, uint32_t& lo) {
    uint32_t h, l;
    asm("cvt.rna.tf32.f32 %0, %1;" : "=r"(h) : "f"(x));
    float r = x - __uint_as_float(h);
    asm("cvt.rna.tf32.f32 %0, %1;" : "=r"(l) : "f"(r));
    hi = h; lo = l;
}

// ---- warp mma m16n8k8 tf32 (sm_80+; legal on plain sm_103 target) ----
__device__ __forceinline__ void mma8(float d[4], const uint32_t a[4],
                                     uint32_t b0, uint32_t b1) {
    asm("mma.sync.aligned.m16n8k8.row.col.f32.tf32.tf32.f32 "
        "{%0,%1,%2,%3}, {%4,%5,%6,%7}, {%8,%9}, {%0,%1,%2,%3};"
        : "+f"(d[0]), "+f"(d[1]), "+f"(d[2]), "+f"(d[3])
        : "r"(a[0]), "r"(a[1]), "r"(a[2]), "r"(a[3]), "r"(b0), "r"(b1));
}

// ---- main kernel -------------------------------------------------------------
__global__ void __launch_bounds__(NTHREADS, 1) vq_mma_kernel(
    const float* __restrict__ enc,
    const float* __restrict__ cb,
    float* __restrict__ out)
{
    extern __shared__ __align__(16) char smem[];
    float* csq_s = reinterpret_cast<float*>(smem + SM_CSQ);
    int*   sidx  = reinterpret_cast<int*>(smem + SM_IDX);
    float* sB    = reinterpret_cast<float*>(smem + SM_B);
    // buffer b: hi split at (2b), lo split at (2b+1)
#define BH(b) (sB + (size_t)(2 * (b)) * (TK * SC_STRIDE))
#define BL(b) (sB + (size_t)(2 * (b) + 1) * (TK * SC_STRIDE))

    const int tid  = threadIdx.x;
    const int lane = tid & 31;
    const int wid  = tid >> 5;
    const int gID  = lane >> 2;   // group id (row within warp's 16-point slab)
    const int tig  = lane & 3;    // thread-in-group (k / col pairing)
    const int pbase = blockIdx.x * TM;

    // ---- A fragments: 16 points x 64 dims, tf32 hi/lo, resident in registers ----
    uint32_t ah[8][4], al[8][4];
    {
        const float* e0 = enc + (size_t)(pbase + wid * 16 + gID) * DIMS;
        const float* e1 = e0 + 8 * DIMS;
#pragma unroll
        for (int kk = 0; kk < 8; kk++) {
            int k0 = kk * 8 + tig;
            tf32_split(e0[k0],     ah[kk][0], al[kk][0]);  // a0: (row g,   k)
            tf32_split(e1[k0],     ah[kk][1], al[kk][1]);  // a1: (row g+8, k)
            tf32_split(e0[k0 + 4], ah[kk][2], al[kk][2]);  // a2: (row g,   k+4)
            tf32_split(e1[k0 + 4], ah[kk][3], al[kk][3]);  // a3: (row g+8, k+4)
        }
    }

    // ---- load code tile 0 into buffer 0 (thread: code = tid/2, dim-half = tid&1) ----
    {
        const int c = tid >> 1, h = tid & 1;
        const float4* src = reinterpret_cast<const float4*>(cb + (size_t)c * DIMS + h * 32);
        uint32_t* dh = reinterpret_cast<uint32_t*>(BH(0) + c * SC_STRIDE + h * 32);
        uint32_t* dl = reinterpret_cast<uint32_t*>(BL(0) + c * SC_STRIDE + h * 32);
#pragma unroll
        for (int q = 0; q < 8; q++) {
            float4 v = src[q];
            uint4 hq, lq;
            tf32_split(v.x, hq.x, lq.x);
            tf32_split(v.y, hq.y, lq.y);
            tf32_split(v.z, hq.z, lq.z);
            tf32_split(v.w, hq.w, lq.w);
            *reinterpret_cast<uint4*>(dh + q * 4) = hq;
            *reinterpret_cast<uint4*>(dl + q * 4) = lq;
        }
        if (tid < 128) csq_s[tid] = g_csq[tid];
    }
    __syncthreads();

    float bd0 = 3.402823466e38f, bd1 = 3.402823466e38f;
    int   bi0 = 0, bi1 = 0;

#pragma unroll 1
    for (int t = 0; t < NTILES; t++) {
        const int buf = t & 1;
        const bool hasNext = (t + 1 < NTILES);

        // ---- register prefetch of tile t+1 (overlaps MMA compute) ----
        float4 pf[8];
        float  pcs = 0.f;
        if (hasNext) {
            const int c = tid >> 1, h = tid & 1;
            const float4* src = reinterpret_cast<const float4*>(
                cb + ((size_t)(t + 1) * TK + c) * DIMS + h * 32);
#pragma unroll
            for (int q = 0; q < 8; q++) pf[q] = src[q];
            if (tid < 128) pcs = g_csq[(t + 1) * TK + tid];
        }

        // ---- compute: 4 groups of 4 n-tiles, 4 independent accumulator chains ----
        const uint32_t* bhp = reinterpret_cast<const uint32_t*>(BH(buf));
        const uint32_t* blp = reinterpret_cast<const uint32_t*>(BL(buf));
        const float* cst = csq_s + buf * 128;

#pragma unroll
        for (int jg = 0; jg < 4; jg++) {
            float d[4][4];
#pragma unroll
            for (int u = 0; u < 4; u++)
#pragma unroll
                for (int e = 0; e < 4; e++) d[u][e] = 0.f;

#pragma unroll
            for (int kk = 0; kk < 8; kk++) {
                const int krow = kk * 8 + tig;
#pragma unroll
                for (int u = 0; u < 4; u++) {
                    const int n = (jg * 4 + u) * 8 + gID;      // code row in tile
                    const int boff = n * SC_STRIDE + krow;
                    uint32_t bh0 = bhp[boff], bh1 = bhp[boff + 4];
                    uint32_t bl0 = blp[boff], bl1 = blp[boff + 4];
                    mma8(d[u], ah[kk], bl0, bl1);   // hi_a . lo_b
                    mma8(d[u], al[kk], bh0, bh1);   // lo_a . hi_b
                    mma8(d[u], ah[kk], bh0, bh1);   // hi_a . hi_b
                }
            }

            // ---- epilogue: dist = csq - 2*dot; ascending-index strict < ----
#pragma unroll
            for (int u = 0; u < 4; u++) {
                const int colb = (jg * 4 + u) * 8 + 2 * tig;
                const int gidx = t * TK + colb;
                const float cs0 = cst[colb], cs1 = cst[colb + 1];
                float e00 = fmaf(-2.f, d[u][0], cs0);
                float e01 = fmaf(-2.f, d[u][1], cs1);
                float e10 = fmaf(-2.f, d[u][2], cs0);
                float e11 = fmaf(-2.f, d[u][3], cs1);
                if (e00 < bd0) { bd0 = e00; bi0 = gidx; }
                if (e01 < bd0) { bd0 = e01; bi0 = gidx + 1; }
                if (e10 < bd1) { bd1 = e10; bi1 = gidx; }
                if (e11 < bd1) { bd1 = e11; bi1 = gidx + 1; }
            }
        }

        // ---- store prefetched tile into the other buffer (free since last sync) ----
        if (hasNext) {
            const int nb = buf ^ 1;
            const int c = tid >> 1, h = tid & 1;
            uint32_t* dh = reinterpret_cast<uint32_t*>(BH(nb) + c * SC_STRIDE + h * 32);
            uint32_t* dl = reinterpret_cast<uint32_t*>(BL(nb) + c * SC_STRIDE + h * 32);
#pragma unroll
            for (int q = 0; q < 8; q++) {
                uint4 hq, lq;
                tf32_split(pf[q].x, hq.x, lq.x);
                tf32_split(pf[q].y, hq.y, lq.y);
                tf32_split(pf[q].z, hq.z, lq.z);
                tf32_split(pf[q].w, hq.w, lq.w);
                *reinterpret_cast<uint4*>(dh + q * 4) = hq;
                *reinterpret_cast<uint4*>(dl + q * 4) = lq;
            }
            if (tid < 128) csq_s[nb * 128 + tid] = pcs;
        }
        __syncthreads();
    }

    // ---- reduce across the 4 lanes of each row group (lexicographic: earliest idx) ----
#pragma unroll
    for (int m = 1; m < 4; m <<= 1) {
        float od0 = __shfl_xor_sync(0xFFFFFFFFu, bd0, m);
        int   oi0 = __shfl_xor_sync(0xFFFFFFFFu, bi0, m);
        float od1 = __shfl_xor_sync(0xFFFFFFFFu, bd1, m);
        int   oi1 = __shfl_xor_sync(0xFFFFFFFFu, bi1, m);
        if (od0 < bd0 || (od0 == bd0 && oi0 < bi0)) { bd0 = od0; bi0 = oi0; }
        if (od1 < bd1 || (od1 == bd1 && oi1 < bi1)) { bd1 = od1; bi1 = oi1; }
    }
    if (tig == 0) {
        sidx[wid * 16 + gID]     = bi0;
        sidx[wid * 16 + gID + 8] = bi1;
    }
    __syncthreads();

    // ---- gather: out[p] = codebook[argmin] (exact fp32 row copy) ----
    {
        const int r = tid >> 1, h = tid & 1;
        const int ci = sidx[r];
        const float4* src = reinterpret_cast<const float4*>(cb + (size_t)ci * DIMS + h * 32);
        float4* dst = reinterpret_cast<float4*>(out + (size_t)(pbase + r) * DIMS + h * 32);
#pragma unroll
        for (int q = 0; q < 8; q++) dst[q] = src[q];
    }
#undef BH
#undef BL
}

// ---- launcher ---------------------------------------------------------------------
extern "C" void kernel_launch(void* const* d_in, const int* in_sizes, int n_in,
                              void* d_out, int out_size) {
    const float* enc = (const float*)d_in[0];
    const float* cb  = (const float*)d_in[1];
    float* out = (float*)d_out;

    static bool attr_set = false;
    if (!attr_set) {
        cudaFuncSetAttribute(vq_mma_kernel, cudaFuncAttributeMaxDynamicSharedMemorySize,
                             (int)SMEM_BYTES);
        attr_set = true;
    }

    csq_kernel<<<K_CODES / 256, 256>>>(cb);
    vq_mma_kernel<<<N_PTS / TM, NTHREADS, SMEM_BYTES>>>(enc, cb, out);
}